// round 1
// baseline (speedup 1.0000x reference)
#include <cuda_runtime.h>

#define BB    16
#define CIN   512
#define COUT  512
#define RES   64
#define WDIM  512

// scratch (device globals — no allocations allowed)
__device__ float g_styles[BB * CIN];    // 32 KB
__device__ float g_wsqT[CIN * COUT];    // 1 MB, transposed: [cin][cout]
__device__ float g_dcoefs[BB * COUT];   // 32 KB

// ---------------------------------------------------------------------------
// Kernel 1: styles[b,cin] = m1*m2 + m3 from the affine projection
// grid = B, block = 512 (one thread per cin)
// ---------------------------------------------------------------------------
__global__ void k_styles(const float* __restrict__ w,
                         const float* __restrict__ affine_w,
                         const float* __restrict__ affine_b) {
    const int b = blockIdx.x;
    const int t = threadIdx.x;               // cin index
    __shared__ float sw[WDIM];
    sw[t] = w[b * WDIM + t];
    __syncthreads();

    const float gain = 1.0f / sqrtf((float)WDIM);
    float m[3];
#pragma unroll
    for (int j0 = 0; j0 < 3; j0++) {
        const int j = j0 * CIN + t;
        const float* __restrict__ row = affine_w + (size_t)j * WDIM;
        float acc = 0.f;
        for (int k = 0; k < WDIM; k++) acc += row[k] * sw[k];
        m[j0] = acc * gain + affine_b[j];
    }
    g_styles[b * CIN + t] = m[0] * m[1] + m[2];
}

// ---------------------------------------------------------------------------
// Kernel 2: wsqT[cin][cout] = sum_{kh,kw} weight[cout,cin,kh,kw]^2
// ---------------------------------------------------------------------------
__global__ void k_wsq(const float* __restrict__ weight) {
    const int id = blockIdx.x * blockDim.x + threadIdx.x;  // CIN*COUT threads
    const int cin  = id / COUT;
    const int cout = id - cin * COUT;
    const float* __restrict__ p = weight + ((size_t)cout * CIN + cin) * 9;
    float s = 0.f;
#pragma unroll
    for (int i = 0; i < 9; i++) { float v = p[i]; s += v * v; }
    g_wsqT[cin * COUT + cout] = s;
}

// ---------------------------------------------------------------------------
// Kernel 3: dcoefs[b,cout] = rsqrt( sum_cin styles^2 * wsqT + 1e-8 )
// grid = B, block = 512 (one thread per cout)
// ---------------------------------------------------------------------------
__global__ void k_dcoefs() {
    const int b = blockIdx.x;
    const int t = threadIdx.x;               // cout
    __shared__ float s2[CIN];
    const float st = g_styles[b * CIN + t];  // CIN == COUT == 512
    s2[t] = st * st;
    __syncthreads();
    float acc = 0.f;
    for (int cin = 0; cin < CIN; cin++)
        acc += s2[cin] * g_wsqT[cin * COUT + t];
    g_dcoefs[b * COUT + t] = rsqrtf(acc + 1e-8f);
}

// ---------------------------------------------------------------------------
// Kernel 4: conv (shared weight, input modulated on load, output demodulated)
// CTA: 16x16 spatial tile x 64 couts.  256 threads.
// thread: 2x2 pixels x 16 couts = 64 fp32 accumulators.
// cin processed in chunks of 8 through smem.
// ---------------------------------------------------------------------------
__global__ __launch_bounds__(256, 2)
void k_conv(const float* __restrict__ x,
            const float* __restrict__ weight,
            const float* __restrict__ bias,
            const float* __restrict__ noise_const,
            const float* __restrict__ noise_strength,
            float* __restrict__ out) {
    const int sp    = blockIdx.x;            // 0..15 spatial tile
    const int cout0 = blockIdx.y * 64;       // 0..7  cout tile
    const int b     = blockIdx.z;            // batch
    const int h0 = (sp >> 2) * 16;
    const int w0 = (sp & 3) * 16;

    const int tid = threadIdx.x;
    const int pc  = tid >> 6;                // 0..3  cout sub-group
    const int pid = tid & 63;                // 0..63 pixel sub-tile
    const int py  = (pid >> 3) * 2;          // pixel row base (0..14, even)
    const int px  = (pid & 7) * 2;           // pixel col base (0..14, even)
    const int cb  = pc * 16;                 // local cout base

    __shared__ float sx[8][18][19];                   // x tile + halo (10.9 KB)
    __shared__ __align__(16) float swt[8 * 9 * 64];   // weights (18.4 KB)

    float acc[4][16];
#pragma unroll
    for (int p = 0; p < 4; p++)
#pragma unroll
        for (int c = 0; c < 16; c++) acc[p][c] = 0.f;

    for (int cin0 = 0; cin0 < CIN; cin0 += 8) {
        __syncthreads();   // previous chunk's reads done before overwrite

        // ---- load x tile (8 cins x 18x18, zero-padded), modulated by styles
#pragma unroll
        for (int l = 0; l < 11; l++) {
            const int idx = tid + l * 256;
            if (idx < 8 * 324) {
                const int cc  = idx / 324;
                const int rem = idx - cc * 324;
                const int r   = rem / 18;
                const int col = rem - r * 18;
                const int gh = h0 + r - 1;
                const int gw = w0 + col - 1;
                float v = 0.f;
                if ((unsigned)gh < 64u && (unsigned)gw < 64u)
                    v = x[(((size_t)b * CIN + cin0 + cc) * RES + gh) * RES + gw]
                        * g_styles[b * CIN + cin0 + cc];
                sx[cc][r][col] = v;
            }
        }

        // ---- load weight tile: swt[(cc*9+tap)*64 + c] = weight[cout0+c][cin0+cc][tap]
        {
            const int c = tid >> 2;          // 0..63 local cout
            const int p = tid & 3;
            const float* __restrict__ row =
                weight + ((size_t)(cout0 + c) * CIN + cin0) * 9 + p * 18;
#pragma unroll
            for (int i = 0; i < 18; i++) {
                const int j = p * 18 + i;    // j = cc*9 + tap  (0..71)
                swt[j * 64 + c] = row[i];
            }
        }
        __syncthreads();

        // ---- compute
#pragma unroll 1
        for (int cc = 0; cc < 8; cc++) {
            float xv[4][4];
#pragma unroll
            for (int r = 0; r < 4; r++)
#pragma unroll
                for (int q = 0; q < 4; q++)
                    xv[r][q] = sx[cc][py + r][px + q];

#pragma unroll
            for (int dh = 0; dh < 3; dh++)
#pragma unroll
            for (int dw = 0; dw < 3; dw++) {
                const float4* __restrict__ wp =
                    (const float4*)&swt[(cc * 9 + dh * 3 + dw) * 64 + cb];
                const float x00 = xv[dh][dw];
                const float x01 = xv[dh][dw + 1];
                const float x10 = xv[dh + 1][dw];
                const float x11 = xv[dh + 1][dw + 1];
#pragma unroll
                for (int cg = 0; cg < 4; cg++) {
                    const float4 w4 = wp[cg];
                    acc[0][cg*4+0] += x00 * w4.x; acc[0][cg*4+1] += x00 * w4.y;
                    acc[0][cg*4+2] += x00 * w4.z; acc[0][cg*4+3] += x00 * w4.w;
                    acc[1][cg*4+0] += x01 * w4.x; acc[1][cg*4+1] += x01 * w4.y;
                    acc[1][cg*4+2] += x01 * w4.z; acc[1][cg*4+3] += x01 * w4.w;
                    acc[2][cg*4+0] += x10 * w4.x; acc[2][cg*4+1] += x10 * w4.y;
                    acc[2][cg*4+2] += x10 * w4.z; acc[2][cg*4+3] += x10 * w4.w;
                    acc[3][cg*4+0] += x11 * w4.x; acc[3][cg*4+1] += x11 * w4.y;
                    acc[3][cg*4+2] += x11 * w4.z; acc[3][cg*4+3] += x11 * w4.w;
                }
            }
        }
    }

    // ---- epilogue: demodulate, noise, bias, lrelu * sqrt(2)
    const float nstr = noise_strength[0];
    float nz[4];
#pragma unroll
    for (int p = 0; p < 4; p++) {
        const int hh = h0 + py + (p >> 1);
        const int ww = w0 + px + (p & 1);
        nz[p] = noise_const[hh * RES + ww] * nstr;
    }
#pragma unroll
    for (int c = 0; c < 16; c++) {
        const int co   = cout0 + cb + c;
        const float dc = g_dcoefs[b * COUT + co];
        const float bi = bias[co];
#pragma unroll
        for (int p = 0; p < 4; p++) {
            const int hh = h0 + py + (p >> 1);
            const int ww = w0 + px + (p & 1);
            float v = acc[p][c] * dc + nz[p] + bi;
            v = (v > 0.f ? v : 0.2f * v) * 1.4142135623730951f;
            out[(((size_t)b * COUT + co) * RES + hh) * RES + ww] = v;
        }
    }
}

// ---------------------------------------------------------------------------
// launch
// ---------------------------------------------------------------------------
extern "C" void kernel_launch(void* const* d_in, const int* in_sizes, int n_in,
                              void* d_out, int out_size) {
    (void)in_sizes; (void)n_in; (void)out_size;
    const float* x              = (const float*)d_in[0];
    const float* w              = (const float*)d_in[1];
    const float* affine_w       = (const float*)d_in[2];
    const float* affine_b       = (const float*)d_in[3];
    const float* weight         = (const float*)d_in[4];
    const float* bias           = (const float*)d_in[5];
    const float* noise_const    = (const float*)d_in[6];
    const float* noise_strength = (const float*)d_in[7];
    float* out = (float*)d_out;

    k_styles<<<BB, 512>>>(w, affine_w, affine_b);
    k_wsq<<<(CIN * COUT) / 256, 256>>>(weight);
    k_dcoefs<<<BB, 512>>>();

    dim3 grid(16, COUT / 64, BB);
    k_conv<<<grid, 256>>>(x, weight, bias, noise_const, noise_strength, out);
}